// round 2
// baseline (speedup 1.0000x reference)
#include <cuda_runtime.h>
#include <math.h>

// Problem constants (fixed shapes from reference)
#define B 4
#define S 512
#define T 256
#define H 1024
#define V 32000

// Scratch (device globals — no allocations allowed)
__device__ float g_enc[B * S * H];     // tanh(E @ W + b)   [B,S,H]  8 MB
__device__ float g_scores[B * T * S];  // dec @ enc^T + bias [B,T,S] 2 MB

// ---------------------------------------------------------------------------
// Kernel 1: enc = tanh(E @ W + b)
// E: [M=B*S, K=H] row-major, W: [K=H, N=H] row-major. Classic 128x128x8 SGEMM,
// 256 threads, 8x8 per-thread tile.
// ---------------------------------------------------------------------------
#define G1_BM 128
#define G1_BN 128
#define G1_BK 8

__global__ __launch_bounds__(256) void gemm1_tanh(
    const float* __restrict__ A,     // [M,K]
    const float* __restrict__ Wp,    // [K,N]
    const float* __restrict__ bias,  // [N]
    int M, int N, int K)
{
    __shared__ float As[G1_BK][G1_BM];
    __shared__ float Bs[G1_BK][G1_BN];

    const int tid = threadIdx.x;
    const int bm = blockIdx.y * G1_BM;
    const int bn = blockIdx.x * G1_BN;
    const int tx = tid & 15;   // 0..15 -> N
    const int ty = tid >> 4;   // 0..15 -> M

    // Load mapping
    const int aRow  = tid >> 1;           // 0..127
    const int aCol4 = (tid & 1) * 4;      // 0 or 4
    const int bRow  = tid >> 5;           // 0..7
    const int bCol4 = (tid & 31) * 4;     // 0..124

    float acc[8][8] = {};

    const float* Aptr = A + (size_t)(bm + aRow) * K + aCol4;
    const float* Bptr = Wp + (size_t)bRow * N + bn + bCol4;

    for (int k0 = 0; k0 < K; k0 += G1_BK) {
        float4 a = *(const float4*)(Aptr + k0);
        As[aCol4 + 0][aRow] = a.x;
        As[aCol4 + 1][aRow] = a.y;
        As[aCol4 + 2][aRow] = a.z;
        As[aCol4 + 3][aRow] = a.w;
        float4 b4 = *(const float4*)(Bptr + (size_t)k0 * N);
        *(float4*)&Bs[bRow][bCol4] = b4;
        __syncthreads();

#pragma unroll
        for (int k = 0; k < G1_BK; k++) {
            float af[8], bf[8];
            *(float4*)&af[0] = *(const float4*)&As[k][ty * 8];
            *(float4*)&af[4] = *(const float4*)&As[k][ty * 8 + 4];
            *(float4*)&bf[0] = *(const float4*)&Bs[k][tx * 8];
            *(float4*)&bf[4] = *(const float4*)&Bs[k][tx * 8 + 4];
#pragma unroll
            for (int i = 0; i < 8; i++)
#pragma unroll
                for (int j = 0; j < 8; j++)
                    acc[i][j] = fmaf(af[i], bf[j], acc[i][j]);
        }
        __syncthreads();
    }

#pragma unroll
    for (int i = 0; i < 8; i++) {
        const int row = bm + ty * 8 + i;
#pragma unroll
        for (int j = 0; j < 8; j += 4) {
            const int col = bn + tx * 8 + j;
            float4 o;
            o.x = tanhf(acc[i][j + 0] + bias[col + 0]);
            o.y = tanhf(acc[i][j + 1] + bias[col + 1]);
            o.z = tanhf(acc[i][j + 2] + bias[col + 2]);
            o.w = tanhf(acc[i][j + 3] + bias[col + 3]);
            *(float4*)&g_enc[(size_t)row * N + col] = o;
        }
    }
}

// ---------------------------------------------------------------------------
// Kernel 2: scores[b,t,s] = sum_h dec[b,t,h]*enc[b,s,h] + input_bias[b,s]
// NT batched GEMM. 64x64x16 tiles, 256 threads, 4x4 per-thread tile.
// Grid: (S/64, T/64, B) = (8, 4, 4) = 128 blocks.
// ---------------------------------------------------------------------------
#define G2_BM 64
#define G2_BN 64
#define G2_BK 16

__global__ __launch_bounds__(256) void gemm2_scores(
    const float* __restrict__ Dec,   // [B,T,H]
    const float* __restrict__ ib)    // [B,S]
{
    __shared__ float As[G2_BK][G2_BM];  // [h][t]
    __shared__ float Bs[G2_BK][G2_BN];  // [h][s]

    const int b  = blockIdx.z;
    const int bt = blockIdx.y * G2_BM;
    const int bs = blockIdx.x * G2_BN;
    const int tid = threadIdx.x;
    const int tx = tid & 15;
    const int ty = tid >> 4;

    const int lr  = tid >> 2;          // 0..63
    const int lc4 = (tid & 3) * 4;     // 0,4,8,12

    const float* Ab = Dec + (size_t)b * T * H + (size_t)(bt + lr) * H + lc4;
    const float* Bb = g_enc + (size_t)b * S * H + (size_t)(bs + lr) * H + lc4;

    float acc[4][4] = {};

    for (int k0 = 0; k0 < H; k0 += G2_BK) {
        float4 a = *(const float4*)(Ab + k0);
        As[lc4 + 0][lr] = a.x;
        As[lc4 + 1][lr] = a.y;
        As[lc4 + 2][lr] = a.z;
        As[lc4 + 3][lr] = a.w;
        float4 bv = *(const float4*)(Bb + k0);
        Bs[lc4 + 0][lr] = bv.x;
        Bs[lc4 + 1][lr] = bv.y;
        Bs[lc4 + 2][lr] = bv.z;
        Bs[lc4 + 3][lr] = bv.w;
        __syncthreads();

#pragma unroll
        for (int k = 0; k < G2_BK; k++) {
            float af[4], bf[4];
            *(float4*)af = *(const float4*)&As[k][ty * 4];
            *(float4*)bf = *(const float4*)&Bs[k][tx * 4];
#pragma unroll
            for (int i = 0; i < 4; i++)
#pragma unroll
                for (int j = 0; j < 4; j++)
                    acc[i][j] = fmaf(af[i], bf[j], acc[i][j]);
        }
        __syncthreads();
    }

#pragma unroll
    for (int i = 0; i < 4; i++) {
        const int t = bt + ty * 4 + i;
        float* orow = &g_scores[((size_t)b * T + t) * S];
#pragma unroll
        for (int j = 0; j < 4; j++) {
            const int s = bs + tx * 4 + j;
            orow[s] = acc[i][j] + ib[b * S + s];
        }
    }
}

// ---------------------------------------------------------------------------
// Kernel 3: per (b,t) row — zero vocab slice, softmax over S, scatter-add.
// Each block owns out[b,t,:] exclusively; atomics only for duplicate ids
// within the row.
// ---------------------------------------------------------------------------
__global__ __launch_bounds__(256) void softmax_scatter(
    const int* __restrict__ ids,     // [B,S]
    float* __restrict__ out)         // [B,T,V]
{
    const int bt = blockIdx.x;       // 0..B*T-1
    const int b = bt / T;
    const int tid = threadIdx.x;

    const float* row = &g_scores[(size_t)bt * S];
    float* orow = out + (size_t)bt * V;

    // Zero the vocab slice (V = 32000 = 8000 float4)
    const float4 z = make_float4(0.f, 0.f, 0.f, 0.f);
    float4* orow4 = (float4*)orow;
    for (int i = tid; i < V / 4; i += 256) orow4[i] = z;

    __shared__ float sm[S];
    __shared__ float red[256];

    // Max
    float m = -INFINITY;
    for (int s = tid; s < S; s += 256) {
        float v = row[s];
        sm[s] = v;
        m = fmaxf(m, v);
    }
    red[tid] = m;
    __syncthreads();
    for (int off = 128; off > 0; off >>= 1) {
        if (tid < off) red[tid] = fmaxf(red[tid], red[tid + off]);
        __syncthreads();
    }
    const float mx = red[0];
    __syncthreads();

    // Exp + sum
    float sum = 0.f;
    for (int s = tid; s < S; s += 256) {
        float e = expf(sm[s] - mx);
        sm[s] = e;
        sum += e;
    }
    red[tid] = sum;
    __syncthreads();
    for (int off = 128; off > 0; off >>= 1) {
        if (tid < off) red[tid] += red[tid + off];
        __syncthreads();
    }
    const float inv = 1.0f / red[0];
    __syncthreads();  // also orders the zeroing writes before the atomics

    // Scatter (duplicate ids within a row need atomics; rows are disjoint)
    const int* brow = ids + b * S;
    for (int s = tid; s < S; s += 256) {
        atomicAdd(&orow[brow[s]], sm[s] * inv);
    }
}

// ---------------------------------------------------------------------------
extern "C" void kernel_launch(void* const* d_in, const int* in_sizes, int n_in,
                              void* d_out, int out_size)
{
    const int*   inputs = (const int*)d_in[0];    // [B,S] int32
    const float* E      = (const float*)d_in[1];  // [B,S,H]
    const float* Dec    = (const float*)d_in[2];  // [B,T,H]
    const float* ib     = (const float*)d_in[3];  // [B,S]
    const float* Wp     = (const float*)d_in[4];  // [H,H]
    const float* bp     = (const float*)d_in[5];  // [H]
    float* out = (float*)d_out;                   // [B,T,V]

    const int M1 = B * S;  // 2048

    dim3 g1(H / G1_BN, M1 / G1_BM);  // (8, 16)
    gemm1_tanh<<<g1, 256>>>(E, Wp, bp, M1, H, H);

    dim3 g2(S / G2_BN, T / G2_BM, B);  // (8, 4, 4)
    gemm2_scores<<<g2, 256>>>(Dec, ib);

    softmax_scatter<<<B * T, 256>>>(inputs, out);
}

// round 4
// speedup vs baseline: 1.3104x; 1.3104x over previous
#include <cuda_runtime.h>
#include <math.h>

typedef unsigned long long ull;

// Problem constants (fixed shapes)
#define B 4
#define S 512
#define T 256
#define H 1024
#define V 32000

// Scratch (device globals — no allocations allowed)
// enc stored TRANSPOSED: g_encT[b][h][s] so gemm2 needs no SMEM transpose.
__device__ float g_encT[B * H * S];    // 8 MB
__device__ float g_scores[B * T * S];  // 2 MB

// Packed fp32x2 FMA (FFMA2) — 2x fp32 throughput vs 3-reg FFMA on sm_103a
__device__ __forceinline__ void fma2(ull& d, ull a, ull b) {
    asm("fma.rn.f32x2 %0, %1, %2, %0;" : "+l"(d) : "l"(a), "l"(b));
}
__device__ __forceinline__ float lo32(ull v) { return __uint_as_float((unsigned)(v)); }
__device__ __forceinline__ float hi32(ull v) { return __uint_as_float((unsigned)(v >> 32)); }

// ---------------------------------------------------------------------------
// Kernel 1: encT[b, n, s] = tanh( (E @ W)[m=(b,s), n] + bias[n] )
// E:[2048,1024] row-major, W:[1024,1024] row-major.
// 64x128 tile, BK=16, 256 threads, double-buffered, f32x2 inner product.
// Grid = (8, 32) = 256 CTAs.
// ---------------------------------------------------------------------------
#define G1_BM 64
#define G1_BN 128
#define G1_BK 16
#define G1_AS 66   // float2 row stride (528 B, multiple of 16)

__global__ __launch_bounds__(256, 2) void gemm1_tanh(
    const float* __restrict__ A,     // [M,K]
    const float* __restrict__ Wp,    // [K,N]
    const float* __restrict__ bias)  // [N]
{
    __shared__ __align__(16) float2 As2[2][G1_BK][G1_AS];   // [k][m] duplicated
    __shared__ __align__(16) float  Bs [2][G1_BK][G1_BN];   // [k][n]

    const int tid = threadIdx.x;
    const int bm = blockIdx.y * G1_BM;
    const int bn = blockIdx.x * G1_BN;
    const int tx = tid & 15;   // n: 16 groups
    const int ty = tid >> 4;   // m: 16 groups of 4 rows

    // A load: 256 float4 per stage, 1 per thread
    const int ar = tid >> 2;            // 0..63
    const int aq = (tid & 3) * 4;       // k sub 0,4,8,12
    const float* Ag = A + (size_t)(bm + ar) * H + aq;

    // B load: 512 float4 per stage, 2 per thread
    const int b0r = tid >> 5;                 // 0..7
    const int b0c = (tid & 31) * 4;
    const int b1r = b0r + 8;                  // 8..15
    const float* Bg0 = Wp + (size_t)b0r * H + bn + b0c;
    const float* Bg1 = Wp + (size_t)b1r * H + bn + b0c;

    ull acc[4][4];
#pragma unroll
    for (int i = 0; i < 4; i++)
#pragma unroll
        for (int j = 0; j < 4; j++) acc[i][j] = 0ull;

    float4 pa  = *(const float4*)(Ag);
    float4 pb0 = *(const float4*)(Bg0);
    float4 pb1 = *(const float4*)(Bg1);

    As2[0][aq + 0][ar] = make_float2(pa.x, pa.x);
    As2[0][aq + 1][ar] = make_float2(pa.y, pa.y);
    As2[0][aq + 2][ar] = make_float2(pa.z, pa.z);
    As2[0][aq + 3][ar] = make_float2(pa.w, pa.w);
    *(float4*)&Bs[0][b0r][b0c] = pb0;
    *(float4*)&Bs[0][b1r][b0c] = pb1;
    __syncthreads();

    const int NIT = H / G1_BK;  // 64
    for (int it = 0; it < NIT; ++it) {
        const int cur = it & 1;
        if (it + 1 < NIT) {
            const int k0 = (it + 1) * G1_BK;
            pa  = *(const float4*)(Ag + k0);
            pb0 = *(const float4*)(Bg0 + (size_t)k0 * H);
            pb1 = *(const float4*)(Bg1 + (size_t)k0 * H);
        }

#pragma unroll
        for (int kk = 0; kk < G1_BK; ++kk) {
            float4 a0 = *(const float4*)&As2[cur][kk][ty * 4];
            float4 a1 = *(const float4*)&As2[cur][kk][ty * 4 + 2];
            float4 f0 = *(const float4*)&Bs[cur][kk][tx * 4];
            float4 f1 = *(const float4*)&Bs[cur][kk][64 + tx * 4];
            ull a2[4], b2[4];
            a2[0] = *(ull*)&a0.x; a2[1] = *(ull*)&a0.z;
            a2[2] = *(ull*)&a1.x; a2[3] = *(ull*)&a1.z;
            b2[0] = *(ull*)&f0.x; b2[1] = *(ull*)&f0.z;
            b2[2] = *(ull*)&f1.x; b2[3] = *(ull*)&f1.z;
#pragma unroll
            for (int i = 0; i < 4; i++)
#pragma unroll
                for (int j = 0; j < 4; j++) fma2(acc[i][j], a2[i], b2[j]);
        }

        if (it + 1 < NIT) {
            const int nxt = cur ^ 1;
            As2[nxt][aq + 0][ar] = make_float2(pa.x, pa.x);
            As2[nxt][aq + 1][ar] = make_float2(pa.y, pa.y);
            As2[nxt][aq + 2][ar] = make_float2(pa.z, pa.z);
            As2[nxt][aq + 3][ar] = make_float2(pa.w, pa.w);
            *(float4*)&Bs[nxt][b0r][b0c] = pb0;
            *(float4*)&Bs[nxt][b1r][b0c] = pb1;
        }
        __syncthreads();
    }

    // Epilogue: bias + tanh -> g_encT[b][h][s]  (transposed write)
    // This thread owns rows s0..s0+3 (consecutive) x 8 h-cols.
    const int bb_ = bm / S;               // batch (tile never crosses batch)
    const int s0  = (bm % S) + ty * 4;
#pragma unroll
    for (int g = 0; g < 2; g++) {
#pragma unroll
        for (int j = 0; j < 4; j++) {
            const int h = bn + g * 64 + tx * 4 + j;
            const float bv = bias[h];
            float4 o;
            float v0, v1, v2, v3;
            if (j == 0) { v0 = lo32(acc[0][2*g]);   v1 = lo32(acc[1][2*g]);   v2 = lo32(acc[2][2*g]);   v3 = lo32(acc[3][2*g]); }
            else if (j == 1) { v0 = hi32(acc[0][2*g]);   v1 = hi32(acc[1][2*g]);   v2 = hi32(acc[2][2*g]);   v3 = hi32(acc[3][2*g]); }
            else if (j == 2) { v0 = lo32(acc[0][2*g+1]); v1 = lo32(acc[1][2*g+1]); v2 = lo32(acc[2][2*g+1]); v3 = lo32(acc[3][2*g+1]); }
            else             { v0 = hi32(acc[0][2*g+1]); v1 = hi32(acc[1][2*g+1]); v2 = hi32(acc[2][2*g+1]); v3 = hi32(acc[3][2*g+1]); }
            o.x = tanhf(v0 + bv);
            o.y = tanhf(v1 + bv);
            o.z = tanhf(v2 + bv);
            o.w = tanhf(v3 + bv);
            *(float4*)&g_encT[((size_t)bb_ * H + h) * S + s0] = o;
        }
    }
}

// ---------------------------------------------------------------------------
// Kernel 2: scores[b,t,s] = sum_h dec[b,t,h]*encT[b,h,s] + input_bias[b,s]
// Now a plain NN GEMM per batch (B tile loads s-contiguous from encT).
// 32x64 tile, BK=32, 128 threads, double-buffered, f32x2.
// Grid = (8, 8, 4) = 256 CTAs.
// ---------------------------------------------------------------------------
#define G2_BM 32
#define G2_BN 64
#define G2_BK 32
#define G2_AS 34   // float2 row stride (272 B, multiple of 16)

__global__ __launch_bounds__(128) void gemm2_scores(
    const float* __restrict__ Dec,   // [B,T,H]
    const float* __restrict__ ib)    // [B,S]
{
    __shared__ __align__(16) float2 As2[2][G2_BK][G2_AS];    // [k][t] duplicated
    __shared__ __align__(16) float  Bs [2][G2_BK][G2_BN];    // [k][s]

    const int b  = blockIdx.z;
    const int bt = blockIdx.y * G2_BM;
    const int bs = blockIdx.x * G2_BN;
    const int tid = threadIdx.x;
    const int tx = tid & 15;   // s: 16 x 4 cols
    const int ty = tid >> 4;   // t: 8 x 4 rows

    // A (dec [t][k] -> SMEM [k][t] dup): 256 f4/stage, 2 per thread
    const int a0r = tid >> 3;             // t-row 0..15
    const int a1r = a0r + 16;             // 16..31
    const int aq  = (tid & 7) * 4;        // k sub
    const float* Ag0 = Dec + ((size_t)b * T + bt + a0r) * H + aq;
    const float* Ag1 = Dec + ((size_t)b * T + bt + a1r) * H + aq;

    // B (encT [k][s], direct): 512 f4/stage, 4 per thread
    const int kr = tid >> 4;              // 0..7 (+8 per rep)
    const int sc = (tid & 15) * 4;
    const float* Bg = g_encT + ((size_t)b * H) * S + bs;   // + k*S + s

    ull acc[4][2];
#pragma unroll
    for (int i = 0; i < 4; i++) { acc[i][0] = 0ull; acc[i][1] = 0ull; }

    float4 pa0, pa1, pb[4];
    pa0 = *(const float4*)(Ag0);
    pa1 = *(const float4*)(Ag1);
#pragma unroll
    for (int r = 0; r < 4; r++)
        pb[r] = *(const float4*)(Bg + (size_t)(kr + r * 8) * S + sc);

#pragma unroll
    for (int i = 0; i < 4; i++) {
        As2[0][aq + i][a0r] = make_float2(((float*)&pa0)[i], ((float*)&pa0)[i]);
        As2[0][aq + i][a1r] = make_float2(((float*)&pa1)[i], ((float*)&pa1)[i]);
    }
#pragma unroll
    for (int r = 0; r < 4; r++)
        *(float4*)&Bs[0][kr + r * 8][sc] = pb[r];
    __syncthreads();

    const int NIT = H / G2_BK;  // 32
    for (int it = 0; it < NIT; ++it) {
        const int cur = it & 1;
        if (it + 1 < NIT) {
            const int k0 = (it + 1) * G2_BK;
            pa0 = *(const float4*)(Ag0 + k0);
            pa1 = *(const float4*)(Ag1 + k0);
#pragma unroll
            for (int r = 0; r < 4; r++)
                pb[r] = *(const float4*)(Bg + (size_t)(k0 + kr + r * 8) * S + sc);
        }

#pragma unroll
        for (int kk = 0; kk < G2_BK; ++kk) {
            float4 a0 = *(const float4*)&As2[cur][kk][ty * 4];
            float4 a1 = *(const float4*)&As2[cur][kk][ty * 4 + 2];
            float4 f0 = *(const float4*)&Bs[cur][kk][tx * 4];
            ull a2[4], b2[2];
            a2[0] = *(ull*)&a0.x; a2[1] = *(ull*)&a0.z;
            a2[2] = *(ull*)&a1.x; a2[3] = *(ull*)&a1.z;
            b2[0] = *(ull*)&f0.x; b2[1] = *(ull*)&f0.z;
#pragma unroll
            for (int i = 0; i < 4; i++) {
                fma2(acc[i][0], a2[i], b2[0]);
                fma2(acc[i][1], a2[i], b2[1]);
            }
        }

        if (it + 1 < NIT) {
            const int nxt = cur ^ 1;
#pragma unroll
            for (int i = 0; i < 4; i++) {
                As2[nxt][aq + i][a0r] = make_float2(((float*)&pa0)[i], ((float*)&pa0)[i]);
                As2[nxt][aq + i][a1r] = make_float2(((float*)&pa1)[i], ((float*)&pa1)[i]);
            }
#pragma unroll
            for (int r = 0; r < 4; r++)
                *(float4*)&Bs[nxt][kr + r * 8][sc] = pb[r];
        }
        __syncthreads();
    }

    // Epilogue: + input_bias, write scores
    const float4 bb = *(const float4*)&ib[b * S + bs + tx * 4];
#pragma unroll
    for (int i = 0; i < 4; i++) {
        const int t = bt + ty * 4 + i;
        float4 o;
        o.x = lo32(acc[i][0]) + bb.x;
        o.y = hi32(acc[i][0]) + bb.y;
        o.z = lo32(acc[i][1]) + bb.z;
        o.w = hi32(acc[i][1]) + bb.w;
        *(float4*)&g_scores[((size_t)b * T + t) * S + bs + tx * 4] = o;
    }
}

// ---------------------------------------------------------------------------
// Kernel 3: per (b,t) row — zero vocab slice, softmax over S, scatter-add.
// ---------------------------------------------------------------------------
__global__ __launch_bounds__(256) void softmax_scatter(
    const int* __restrict__ ids,     // [B,S]
    float* __restrict__ out)         // [B,T,V]
{
    const int bt = blockIdx.x;       // 0..B*T-1
    const int b = bt / T;
    const int tid = threadIdx.x;

    const float* row = &g_scores[(size_t)bt * S];
    float* orow = out + (size_t)bt * V;

    // Zero the vocab slice (V = 32000 = 8000 float4)
    const float4 z = make_float4(0.f, 0.f, 0.f, 0.f);
    float4* orow4 = (float4*)orow;
    for (int i = tid; i < V / 4; i += 256) orow4[i] = z;

    __shared__ float sm[S];
    __shared__ float red[256];

    // Max
    float m = -INFINITY;
    for (int s = tid; s < S; s += 256) {
        float v = row[s];
        sm[s] = v;
        m = fmaxf(m, v);
    }
    red[tid] = m;
    __syncthreads();
    for (int off = 128; off > 0; off >>= 1) {
        if (tid < off) red[tid] = fmaxf(red[tid], red[tid + off]);
        __syncthreads();
    }
    const float mx = red[0];
    __syncthreads();

    // Exp + sum
    float sum = 0.f;
    for (int s = tid; s < S; s += 256) {
        float e = expf(sm[s] - mx);
        sm[s] = e;
        sum += e;
    }
    red[tid] = sum;
    __syncthreads();
    for (int off = 128; off > 0; off >>= 1) {
        if (tid < off) red[tid] += red[tid + off];
        __syncthreads();
    }
    const float inv = 1.0f / red[0];
    __syncthreads();  // orders the zeroing before the atomics

    const int* brow = ids + b * S;
    for (int s = tid; s < S; s += 256) {
        atomicAdd(&orow[brow[s]], sm[s] * inv);
    }
}

// ---------------------------------------------------------------------------
extern "C" void kernel_launch(void* const* d_in, const int* in_sizes, int n_in,
                              void* d_out, int out_size)
{
    const int*   inputs = (const int*)d_in[0];    // [B,S] int32
    const float* E      = (const float*)d_in[1];  // [B,S,H]
    const float* Dec    = (const float*)d_in[2];  // [B,T,H]
    const float* ib     = (const float*)d_in[3];  // [B,S]
    const float* Wp     = (const float*)d_in[4];  // [H,H]
    const float* bp     = (const float*)d_in[5];  // [H]
    float* out = (float*)d_out;                   // [B,T,V]

    dim3 g1(H / G1_BN, (B * S) / G1_BM);  // (8, 32) = 256 CTAs
    gemm1_tanh<<<g1, 256>>>(E, Wp, bp);

    dim3 g2(S / G2_BN, T / G2_BM, B);     // (8, 8, 4) = 256 CTAs
    gemm2_scores<<<g2, 128>>>(Dec, ib);

    softmax_scatter<<<B * T, 256>>>(inputs, out);
}

// round 6
// speedup vs baseline: 1.9754x; 1.5075x over previous
#include <cuda_runtime.h>
#include <cuda_bf16.h>
#include <math.h>
#include <cstdint>

typedef unsigned long long ull;

// Problem constants (fixed shapes)
#define B 4
#define S 512
#define T 256
#define H 1024
#define V 32000
#define M1 (B * S)   // 2048

// Scratch (device globals — no allocations allowed)
__device__ float g_encT[B * H * S];      // enc transposed [b][h][s], 8 MB
__device__ float g_scores[B * T * S];    // [b][t][s], 2 MB
__device__ unsigned short g_Eh[M1 * H];  // bf16 hi of E  [M,K]
__device__ unsigned short g_El[M1 * H];  // bf16 lo of E  [M,K]
__device__ unsigned short g_Wh[H * H];   // bf16 hi of W^T [N,K]
__device__ unsigned short g_Wl[H * H];   // bf16 lo of W^T [N,K]

// ---------------------------------------------------------------------------
// Arch-generic tensor-core primitives (legal on plain sm_103 target)
// ---------------------------------------------------------------------------
#define LDSM4(r, a)                                                            \
    asm volatile("ldmatrix.sync.aligned.m8n8.x4.shared.b16 {%0,%1,%2,%3}, [%4];" \
        : "=r"((r)[0]), "=r"((r)[1]), "=r"((r)[2]), "=r"((r)[3]) : "r"(a))

#define MMA_BF16(d, a, b0, b1)                                                 \
    asm volatile(                                                              \
        "mma.sync.aligned.m16n8k16.row.col.f32.bf16.bf16.f32 "                 \
        "{%0,%1,%2,%3}, {%4,%5,%6,%7}, {%8,%9}, {%0,%1,%2,%3};"                \
        : "+f"((d)[0]), "+f"((d)[1]), "+f"((d)[2]), "+f"((d)[3])               \
        : "r"((a)[0]), "r"((a)[1]), "r"((a)[2]), "r"((a)[3]),                  \
          "r"(b0), "r"(b1))

__device__ __forceinline__ uint32_t smem_to_u32(const void* p) {
    uint32_t a;
    asm("{ .reg .u64 t; cvta.to.shared.u64 t, %1; cvt.u32.u64 %0, t; }"
        : "=r"(a) : "l"(p));
    return a;
}

// ---------------------------------------------------------------------------
// Converter 1: E [M1,H] fp32 -> g_Eh/g_El bf16 (hi/lo split)
// ---------------------------------------------------------------------------
__global__ __launch_bounds__(256) void convert_E(const float* __restrict__ E)
{
    const int idx = blockIdx.x * 256 + threadIdx.x;  // float4 index
    const float4 v = ((const float4*)E)[idx];
    ushort4 h, l;
    const float* vf = (const float*)&v;
    unsigned short* hp = (unsigned short*)&h;
    unsigned short* lp = (unsigned short*)&l;
#pragma unroll
    for (int i = 0; i < 4; i++) {
        __nv_bfloat16 hb = __float2bfloat16_rn(vf[i]);
        hp[i] = __bfloat16_as_ushort(hb);
        lp[i] = __bfloat16_as_ushort(__float2bfloat16_rn(vf[i] - __bfloat162float(hb)));
    }
    ((ushort4*)g_Eh)[idx] = h;
    ((ushort4*)g_El)[idx] = l;
}

// ---------------------------------------------------------------------------
// Converter 2: W [K,N] fp32 -> g_Wh/g_Wl = W^T [N,K] bf16 (tiled transpose)
// ---------------------------------------------------------------------------
__global__ __launch_bounds__(256) void convert_W(const float* __restrict__ W)
{
    __shared__ float t[32][33];
    const int k0 = blockIdx.x * 32;
    const int n0 = blockIdx.y * 32;
    const int tx = threadIdx.x & 31;
    const int ty = threadIdx.x >> 5;  // 0..7
#pragma unroll
    for (int r = 0; r < 4; r++) {
        const int k = ty + r * 8;
        t[k][tx] = W[(size_t)(k0 + k) * H + n0 + tx];
    }
    __syncthreads();
#pragma unroll
    for (int r = 0; r < 4; r++) {
        const int n = ty + r * 8;
        const float x = t[tx][n];
        __nv_bfloat16 hb = __float2bfloat16_rn(x);
        g_Wh[(size_t)(n0 + n) * H + k0 + tx] = __bfloat16_as_ushort(hb);
        g_Wl[(size_t)(n0 + n) * H + k0 + tx] =
            __bfloat16_as_ushort(__float2bfloat16_rn(x - __bfloat162float(hb)));
    }
}

// ---------------------------------------------------------------------------
// GEMM1 via mma.sync (HMMA bf16, fp32 accum), 3-pass hi/lo split.
// CTA tile 128x128, BK=32, 2-stage cp.async pipeline.
// 8 warps = 4(M) x 2(N); warp tile 32x64 = 2 m16 x 8 n8.
// SMEM tiles: 128 rows x 64B, swizzle c' = c ^ ((row>>1)&3) (16B units).
// Epilogue: tanh(D + bias[h]) -> g_encT[b][h][s].
// ---------------------------------------------------------------------------
#define BK1 32
#define TILE_B (128 * 64)         // 8 KB per tile
#define STAGE_B (4 * TILE_B)      // Ah, Al, Bh, Bl = 32 KB
#define SMEM_G1 (2 * STAGE_B)     // 64 KB

__global__ __launch_bounds__(256, 1) void gemm1_mma(const float* __restrict__ bias)
{
    extern __shared__ __align__(128) char smem[];
    const uint32_t sb = smem_to_u32(smem);
    const int tid = threadIdx.x;
    const int lane = tid & 31;
    const int wid = tid >> 5;
    const int wm = wid & 3;           // 0..3 (M)
    const int wn = wid >> 2;          // 0..1 (N)
    const int bm = blockIdx.y * 128;  // (b,s) tile
    const int bn = blockIdx.x * 128;  // h tile

    const unsigned short* srcs[4] = {g_Eh, g_El, g_Wh, g_Wl};

    // Per-thread cp.async mapping (8 x 16B per stage)
    // unit u = tid + 256*i : tile t=u>>9, row=(u&511)>>2, c=(u&511)&3
    float acc[2][8][4];
#pragma unroll
    for (int mt = 0; mt < 2; mt++)
#pragma unroll
        for (int nt = 0; nt < 8; nt++)
#pragma unroll
            for (int q = 0; q < 4; q++) acc[mt][nt][q] = 0.f;

    // ldmatrix per-lane row pieces
    const int arow = lane & 15;   // row within 16
    const int half = lane >> 4;   // 0/1 -> +16B column

#define G1_ISSUE(ch, stage)                                                    \
    do {                                                                       \
        const int _k0 = (ch) * BK1;                                            \
        _Pragma("unroll")                                                      \
        for (int _i = 0; _i < 8; _i++) {                                       \
            const int _u = tid + (_i << 8);                                    \
            const int _t = _u >> 9;                                            \
            const int _rem = _u & 511;                                         \
            const int _row = _rem >> 2;                                        \
            const int _c = _rem & 3;                                           \
            const int _grow = ((_t < 2) ? bm : bn) + _row;                     \
            const void* _g = srcs[_t] + (size_t)_grow * H + _k0 + _c * 8;      \
            const uint32_t _sa = sb + (stage) * STAGE_B + _t * TILE_B          \
                + _row * 64 + (((_c) ^ ((_row >> 1) & 3)) << 4);               \
            asm volatile("cp.async.cg.shared.global [%0], [%1], 16;"           \
                :: "r"(_sa), "l"(_g));                                         \
        }                                                                      \
        asm volatile("cp.async.commit_group;" ::: "memory");                   \
    } while (0)

    G1_ISSUE(0, 0);

    const int NCH = H / BK1;  // 32
    for (int ch = 0; ch < NCH; ++ch) {
        const int st = ch & 1;
        if (ch + 1 < NCH) {
            G1_ISSUE(ch + 1, st ^ 1);
            asm volatile("cp.async.wait_group 1;" ::: "memory");
        } else {
            asm volatile("cp.async.wait_group 0;" ::: "memory");
        }
        __syncthreads();

        const uint32_t base = sb + st * STAGE_B;
#pragma unroll
        for (int ks = 0; ks < 2; ++ks) {          // two k16 steps per BK=32
            const int cb = ks * 2 + half;         // 16B column for this lane
            uint32_t ah[2][4], al[2][4];
#pragma unroll
            for (int mt = 0; mt < 2; ++mt) {
                const int row = wm * 32 + mt * 16 + arow;
                const uint32_t off = row * 64 + ((cb ^ ((row >> 1) & 3)) << 4);
                LDSM4(ah[mt], base + 0 * TILE_B + off);
                LDSM4(al[mt], base + 1 * TILE_B + off);
            }
#pragma unroll
            for (int np = 0; np < 4; ++np) {      // 4 n16 pairs = 8 n8 tiles
                const int row = wn * 64 + np * 16 + arow;
                const uint32_t off = row * 64 + ((cb ^ ((row >> 1) & 3)) << 4);
                uint32_t bh[4], bl[4];
                LDSM4(bh, base + 2 * TILE_B + off);
                LDSM4(bl, base + 3 * TILE_B + off);
#pragma unroll
                for (int mt = 0; mt < 2; ++mt) {
                    // n8 tile 2*np uses regs {0,2}; tile 2*np+1 uses {1,3}
                    MMA_BF16(acc[mt][2 * np],     ah[mt], bh[0], bh[2]);
                    MMA_BF16(acc[mt][2 * np],     al[mt], bh[0], bh[2]);
                    MMA_BF16(acc[mt][2 * np],     ah[mt], bl[0], bl[2]);
                    MMA_BF16(acc[mt][2 * np + 1], ah[mt], bh[1], bh[3]);
                    MMA_BF16(acc[mt][2 * np + 1], al[mt], bh[1], bh[3]);
                    MMA_BF16(acc[mt][2 * np + 1], ah[mt], bl[1], bl[3]);
                }
            }
        }
        __syncthreads();
    }

    // Epilogue: acc row r=lane/4 -> s, col -> h; fuse bias + tanh.
    const int b_ = bm / S;
    const int s_base = (bm % S) + wm * 32 + (lane >> 2);
    const int n_base = bn + wn * 64;
#pragma unroll
    for (int mt = 0; mt < 2; ++mt) {
        const int s0 = s_base + mt * 16;
#pragma unroll
        for (int nt = 0; nt < 8; ++nt) {
            const int n0 = n_base + nt * 8 + 2 * (lane & 3);
            const float bv0 = bias[n0];
            const float bv1 = bias[n0 + 1];
            float* p0 = &g_encT[((size_t)b_ * H + n0) * S];
            float* p1 = &g_encT[((size_t)b_ * H + n0 + 1) * S];
            p0[s0]     = tanhf(acc[mt][nt][0] + bv0);
            p1[s0]     = tanhf(acc[mt][nt][1] + bv1);
            p0[s0 + 8] = tanhf(acc[mt][nt][2] + bv0);
            p1[s0 + 8] = tanhf(acc[mt][nt][3] + bv1);
        }
    }
}

// ---------------------------------------------------------------------------
// Kernel 2 (unchanged): scores = dec @ encT + bias, f32x2 SIMT.
// ---------------------------------------------------------------------------
__device__ __forceinline__ void fma2(ull& d, ull a, ull b) {
    asm("fma.rn.f32x2 %0, %1, %2, %0;" : "+l"(d) : "l"(a), "l"(b));
}
__device__ __forceinline__ float lo32(ull v) { return __uint_as_float((unsigned)(v)); }
__device__ __forceinline__ float hi32(ull v) { return __uint_as_float((unsigned)(v >> 32)); }

#define G2_BM 32
#define G2_BN 64
#define G2_BK 32
#define G2_AS 34

__global__ __launch_bounds__(128) void gemm2_scores(
    const float* __restrict__ Dec, const float* __restrict__ ib)
{
    __shared__ __align__(16) float2 As2[2][G2_BK][G2_AS];
    __shared__ __align__(16) float  Bs [2][G2_BK][G2_BN];

    const int b  = blockIdx.z;
    const int bt = blockIdx.y * G2_BM;
    const int bs = blockIdx.x * G2_BN;
    const int tid = threadIdx.x;
    const int tx = tid & 15;
    const int ty = tid >> 4;

    const int a0r = tid >> 3;
    const int a1r = a0r + 16;
    const int aq  = (tid & 7) * 4;
    const float* Ag0 = Dec + ((size_t)b * T + bt + a0r) * H + aq;
    const float* Ag1 = Dec + ((size_t)b * T + bt + a1r) * H + aq;

    const int kr = tid >> 4;
    const int sc = (tid & 15) * 4;
    const float* Bg = g_encT + ((size_t)b * H) * S + bs;

    ull acc[4][2];
#pragma unroll
    for (int i = 0; i < 4; i++) { acc[i][0] = 0ull; acc[i][1] = 0ull; }

    float4 pa0, pa1, pb[4];
    pa0 = *(const float4*)(Ag0);
    pa1 = *(const float4*)(Ag1);
#pragma unroll
    for (int r = 0; r < 4; r++)
        pb[r] = *(const float4*)(Bg + (size_t)(kr + r * 8) * S + sc);

#pragma unroll
    for (int i = 0; i < 4; i++) {
        As2[0][aq + i][a0r] = make_float2(((float*)&pa0)[i], ((float*)&pa0)[i]);
        As2[0][aq + i][a1r] = make_float2(((float*)&pa1)[i], ((float*)&pa1)[i]);
    }
#pragma unroll
    for (int r = 0; r < 4; r++)
        *(float4*)&Bs[0][kr + r * 8][sc] = pb[r];
    __syncthreads();

    const int NIT = H / G2_BK;
    for (int it = 0; it < NIT; ++it) {
        const int cur = it & 1;
        if (it + 1 < NIT) {
            const int k0 = (it + 1) * G2_BK;
            pa0 = *(const float4*)(Ag0 + k0);
            pa1 = *(const float4*)(Ag1 + k0);
#pragma unroll
            for (int r = 0; r < 4; r++)
                pb[r] = *(const float4*)(Bg + (size_t)(k0 + kr + r * 8) * S + sc);
        }
#pragma unroll
        for (int kk = 0; kk < G2_BK; ++kk) {
            float4 a0 = *(const float4*)&As2[cur][kk][ty * 4];
            float4 a1 = *(const float4*)&As2[cur][kk][ty * 4 + 2];
            float4 f0 = *(const float4*)&Bs[cur][kk][tx * 4];
            ull a2[4], b2[2];
            a2[0] = *(ull*)&a0.x; a2[1] = *(ull*)&a0.z;
            a2[2] = *(ull*)&a1.x; a2[3] = *(ull*)&a1.z;
            b2[0] = *(ull*)&f0.x; b2[1] = *(ull*)&f0.z;
#pragma unroll
            for (int i = 0; i < 4; i++) {
                fma2(acc[i][0], a2[i], b2[0]);
                fma2(acc[i][1], a2[i], b2[1]);
            }
        }
        if (it + 1 < NIT) {
            const int nxt = cur ^ 1;
#pragma unroll
            for (int i = 0; i < 4; i++) {
                As2[nxt][aq + i][a0r] = make_float2(((float*)&pa0)[i], ((float*)&pa0)[i]);
                As2[nxt][aq + i][a1r] = make_float2(((float*)&pa1)[i], ((float*)&pa1)[i]);
            }
#pragma unroll
            for (int r = 0; r < 4; r++)
                *(float4*)&Bs[nxt][kr + r * 8][sc] = pb[r];
        }
        __syncthreads();
    }

    const float4 bb = *(const float4*)&ib[b * S + bs + tx * 4];
#pragma unroll
    for (int i = 0; i < 4; i++) {
        const int t = bt + ty * 4 + i;
        float4 o;
        o.x = lo32(acc[i][0]) + bb.x;
        o.y = hi32(acc[i][0]) + bb.y;
        o.z = lo32(acc[i][1]) + bb.z;
        o.w = hi32(acc[i][1]) + bb.w;
        *(float4*)&g_scores[((size_t)b * T + t) * S + bs + tx * 4] = o;
    }
}

// ---------------------------------------------------------------------------
// Kernel 3 (unchanged): zero vocab slice, softmax over S, scatter-add.
// ---------------------------------------------------------------------------
__global__ __launch_bounds__(256) void softmax_scatter(
    const int* __restrict__ ids, float* __restrict__ out)
{
    const int bt = blockIdx.x;
    const int b = bt / T;
    const int tid = threadIdx.x;

    const float* row = &g_scores[(size_t)bt * S];
    float* orow = out + (size_t)bt * V;

    const float4 z = make_float4(0.f, 0.f, 0.f, 0.f);
    float4* orow4 = (float4*)orow;
    for (int i = tid; i < V / 4; i += 256) orow4[i] = z;

    __shared__ float sm[S];
    __shared__ float red[256];

    float m = -INFINITY;
    for (int s = tid; s < S; s += 256) {
        float v = row[s];
        sm[s] = v;
        m = fmaxf(m, v);
    }
    red[tid] = m;
    __syncthreads();
    for (int off = 128; off > 0; off >>= 1) {
        if (tid < off) red[tid] = fmaxf(red[tid], red[tid + off]);
        __syncthreads();
    }
    const float mx = red[0];
    __syncthreads();

    float sum = 0.f;
    for (int s = tid; s < S; s += 256) {
        float e = expf(sm[s] - mx);
        sm[s] = e;
        sum += e;
    }
    red[tid] = sum;
    __syncthreads();
    for (int off = 128; off > 0; off >>= 1) {
        if (tid < off) red[tid] += red[tid + off];
        __syncthreads();
    }
    const float inv = 1.0f / red[0];
    __syncthreads();

    const int* brow = ids + b * S;
    for (int s = tid; s < S; s += 256) {
        atomicAdd(&orow[brow[s]], sm[s] * inv);
    }
}

// ---------------------------------------------------------------------------
extern "C" void kernel_launch(void* const* d_in, const int* in_sizes, int n_in,
                              void* d_out, int out_size)
{
    const int*   inputs = (const int*)d_in[0];    // [B,S] int32
    const float* E      = (const float*)d_in[1];  // [B,S,H]
    const float* Dec    = (const float*)d_in[2];  // [B,T,H]
    const float* ib     = (const float*)d_in[3];  // [B,S]
    const float* Wp     = (const float*)d_in[4];  // [H,H]
    const float* bp     = (const float*)d_in[5];  // [H]
    float* out = (float*)d_out;                   // [B,T,V]

    cudaFuncSetAttribute(gemm1_mma, cudaFuncAttributeMaxDynamicSharedMemorySize,
                         SMEM_G1);

    convert_E<<<(M1 * H / 4) / 256, 256>>>(E);
    convert_W<<<dim3(H / 32, H / 32), 256>>>(Wp);

    dim3 g1(H / 128, M1 / 128);                   // (8, 16) = 128 CTAs
    gemm1_mma<<<g1, 256, SMEM_G1>>>(bp);

    dim3 g2(S / G2_BN, T / G2_BM, B);             // (8, 8, 4)
    gemm2_scores<<<g2, 128>>>(Dec, ib);

    softmax_scatter<<<B * T, 256>>>(inputs, out);
}

// round 7
// speedup vs baseline: 2.5290x; 1.2802x over previous
#include <cuda_runtime.h>
#include <cuda_bf16.h>
#include <math.h>
#include <cstdint>

// Problem constants (fixed shapes)
#define B 4
#define S 512
#define T 256
#define H 1024
#define V 32000
#define M1 (B * S)   // 2048

// Scratch (device globals — no allocations allowed)
__device__ float g_scores[B * T * S];      // [b][t][s], 2 MB
__device__ unsigned short g_Eh[M1 * H];    // bf16 hi of E   [M,K]
__device__ unsigned short g_El[M1 * H];    // bf16 lo of E   [M,K]
__device__ unsigned short g_Wh[H * H];     // bf16 hi of W^T [N,K]
__device__ unsigned short g_Wl[H * H];     // bf16 lo of W^T [N,K]
__device__ unsigned short g_Ench[B * S * H]; // bf16 hi of enc [b][s][h]
__device__ unsigned short g_Encl[B * S * H]; // bf16 lo of enc [b][s][h]
__device__ unsigned short g_Dech[B * T * H]; // bf16 hi of dec [b][t][h]
__device__ unsigned short g_Decl[B * T * H]; // bf16 lo of dec [b][t][h]

// ---------------------------------------------------------------------------
// Arch-generic tensor-core primitives (legal on plain sm_103 target)
// ---------------------------------------------------------------------------
#define LDSM4(r, a)                                                            \
    asm volatile("ldmatrix.sync.aligned.m8n8.x4.shared.b16 {%0,%1,%2,%3}, [%4];" \
        : "=r"((r)[0]), "=r"((r)[1]), "=r"((r)[2]), "=r"((r)[3]) : "r"(a))

#define MMA_BF16(d, a, b0, b1)                                                 \
    asm volatile(                                                              \
        "mma.sync.aligned.m16n8k16.row.col.f32.bf16.bf16.f32 "                 \
        "{%0,%1,%2,%3}, {%4,%5,%6,%7}, {%8,%9}, {%0,%1,%2,%3};"                \
        : "+f"((d)[0]), "+f"((d)[1]), "+f"((d)[2]), "+f"((d)[3])               \
        : "r"((a)[0]), "r"((a)[1]), "r"((a)[2]), "r"((a)[3]),                  \
          "r"(b0), "r"(b1))

__device__ __forceinline__ uint32_t smem_to_u32(const void* p) {
    uint32_t a;
    asm("{ .reg .u64 t; cvta.to.shared.u64 t, %1; cvt.u32.u64 %0, t; }"
        : "=r"(a) : "l"(p));
    return a;
}

// Split v into bf16 hi/lo pair; pack two adjacent columns into one 4B store.
__device__ __forceinline__ void split_store2(
    unsigned short* hp, unsigned short* lp, float v0, float v1)
{
    __nv_bfloat16 h0 = __float2bfloat16_rn(v0);
    __nv_bfloat16 h1 = __float2bfloat16_rn(v1);
    unsigned short l0 = __bfloat16_as_ushort(__float2bfloat16_rn(v0 - __bfloat162float(h0)));
    unsigned short l1 = __bfloat16_as_ushort(__float2bfloat16_rn(v1 - __bfloat162float(h1)));
    *(uint32_t*)hp = (uint32_t)__bfloat16_as_ushort(h0) |
                     ((uint32_t)__bfloat16_as_ushort(h1) << 16);
    *(uint32_t*)lp = (uint32_t)l0 | ((uint32_t)l1 << 16);
}

// ---------------------------------------------------------------------------
// Converters: fp32 -> bf16 hi/lo
// ---------------------------------------------------------------------------
__global__ __launch_bounds__(256) void convert_split(
    const float* __restrict__ src, unsigned short* __restrict__ hi,
    unsigned short* __restrict__ lo)
{
    const int idx = blockIdx.x * 256 + threadIdx.x;  // float4 index
    const float4 v = ((const float4*)src)[idx];
    ushort4 h, l;
    const float* vf = (const float*)&v;
    unsigned short* hp = (unsigned short*)&h;
    unsigned short* lp = (unsigned short*)&l;
#pragma unroll
    for (int i = 0; i < 4; i++) {
        __nv_bfloat16 hb = __float2bfloat16_rn(vf[i]);
        hp[i] = __bfloat16_as_ushort(hb);
        lp[i] = __bfloat16_as_ushort(__float2bfloat16_rn(vf[i] - __bfloat162float(hb)));
    }
    ((ushort4*)hi)[idx] = h;
    ((ushort4*)lo)[idx] = l;
}

// W [K,N] fp32 -> W^T [N,K] bf16 hi/lo (tiled transpose)
__global__ __launch_bounds__(256) void convert_W(const float* __restrict__ W)
{
    __shared__ float t[32][33];
    const int k0 = blockIdx.x * 32;
    const int n0 = blockIdx.y * 32;
    const int tx = threadIdx.x & 31;
    const int ty = threadIdx.x >> 5;  // 0..7
#pragma unroll
    for (int r = 0; r < 4; r++) {
        const int k = ty + r * 8;
        t[k][tx] = W[(size_t)(k0 + k) * H + n0 + tx];
    }
    __syncthreads();
#pragma unroll
    for (int r = 0; r < 4; r++) {
        const int n = ty + r * 8;
        const float x = t[tx][n];
        __nv_bfloat16 hb = __float2bfloat16_rn(x);
        g_Wh[(size_t)(n0 + n) * H + k0 + tx] = __bfloat16_as_ushort(hb);
        g_Wl[(size_t)(n0 + n) * H + k0 + tx] =
            __bfloat16_as_ushort(__float2bfloat16_rn(x - __bfloat162float(hb)));
    }
}

// ---------------------------------------------------------------------------
// GEMM1: enc = tanh(E @ W + b), HMMA bf16 hi/lo 3-pass.
// CTA 128x128, BK=32, 2-stage cp.async; 8 warps = 4(M) x 2(N), warp 32x64.
// Epilogue writes enc as bf16 hi/lo in [b][s][h] (B-operand layout for gemm2).
// ---------------------------------------------------------------------------
#define BK1 32
#define TILE_B (128 * 64)         // 8 KB per tile
#define STAGE_B (4 * TILE_B)      // Ah, Al, Bh, Bl = 32 KB
#define SMEM_G1 (2 * STAGE_B)     // 64 KB

__global__ __launch_bounds__(256, 1) void gemm1_mma(const float* __restrict__ bias)
{
    extern __shared__ __align__(128) char smem[];
    const uint32_t sb = smem_to_u32(smem);
    const int tid = threadIdx.x;
    const int lane = tid & 31;
    const int wid = tid >> 5;
    const int wm = wid & 3;           // 0..3 (M)
    const int wn = wid >> 2;          // 0..1 (N)
    const int bm = blockIdx.y * 128;  // (b,s) tile
    const int bn = blockIdx.x * 128;  // h tile

    const unsigned short* srcs[4] = {g_Eh, g_El, g_Wh, g_Wl};

    float acc[2][8][4];
#pragma unroll
    for (int mt = 0; mt < 2; mt++)
#pragma unroll
        for (int nt = 0; nt < 8; nt++)
#pragma unroll
            for (int q = 0; q < 4; q++) acc[mt][nt][q] = 0.f;

    const int arow = lane & 15;
    const int half = lane >> 4;

#define G1_ISSUE(ch, stage)                                                    \
    do {                                                                       \
        const int _k0 = (ch) * BK1;                                            \
        _Pragma("unroll")                                                      \
        for (int _i = 0; _i < 8; _i++) {                                       \
            const int _u = tid + (_i << 8);                                    \
            const int _t = _u >> 9;                                            \
            const int _rem = _u & 511;                                         \
            const int _row = _rem >> 2;                                        \
            const int _c = _rem & 3;                                           \
            const int _grow = ((_t < 2) ? bm : bn) + _row;                     \
            const void* _g = srcs[_t] + (size_t)_grow * H + _k0 + _c * 8;      \
            const uint32_t _sa = sb + (stage) * STAGE_B + _t * TILE_B          \
                + _row * 64 + (((_c) ^ ((_row >> 1) & 3)) << 4);               \
            asm volatile("cp.async.cg.shared.global [%0], [%1], 16;"           \
                :: "r"(_sa), "l"(_g));                                         \
        }                                                                      \
        asm volatile("cp.async.commit_group;" ::: "memory");                   \
    } while (0)

    G1_ISSUE(0, 0);

    const int NCH = H / BK1;  // 32
    for (int ch = 0; ch < NCH; ++ch) {
        const int st = ch & 1;
        if (ch + 1 < NCH) {
            G1_ISSUE(ch + 1, st ^ 1);
            asm volatile("cp.async.wait_group 1;" ::: "memory");
        } else {
            asm volatile("cp.async.wait_group 0;" ::: "memory");
        }
        __syncthreads();

        const uint32_t base = sb + st * STAGE_B;
#pragma unroll
        for (int ks = 0; ks < 2; ++ks) {
            const int cb = ks * 2 + half;
            uint32_t ah[2][4], al[2][4];
#pragma unroll
            for (int mt = 0; mt < 2; ++mt) {
                const int row = wm * 32 + mt * 16 + arow;
                const uint32_t off = row * 64 + ((cb ^ ((row >> 1) & 3)) << 4);
                LDSM4(ah[mt], base + 0 * TILE_B + off);
                LDSM4(al[mt], base + 1 * TILE_B + off);
            }
#pragma unroll
            for (int np = 0; np < 4; ++np) {
                const int row = wn * 64 + np * 16 + arow;
                const uint32_t off = row * 64 + ((cb ^ ((row >> 1) & 3)) << 4);
                uint32_t bh[4], bl[4];
                LDSM4(bh, base + 2 * TILE_B + off);
                LDSM4(bl, base + 3 * TILE_B + off);
#pragma unroll
                for (int mt = 0; mt < 2; ++mt) {
                    MMA_BF16(acc[mt][2 * np],     ah[mt], bh[0], bh[2]);
                    MMA_BF16(acc[mt][2 * np],     al[mt], bh[0], bh[2]);
                    MMA_BF16(acc[mt][2 * np],     ah[mt], bl[0], bl[2]);
                    MMA_BF16(acc[mt][2 * np + 1], ah[mt], bh[1], bh[3]);
                    MMA_BF16(acc[mt][2 * np + 1], al[mt], bh[1], bh[3]);
                    MMA_BF16(acc[mt][2 * np + 1], ah[mt], bl[1], bl[3]);
                }
            }
        }
        __syncthreads();
    }

    // Epilogue: tanh(D + bias[h]) split to bf16 hi/lo, stored [b][s][h].
    const int b_ = bm / S;
    const int s_base = (bm % S) + wm * 32 + (lane >> 2);
    const int n_base = bn + wn * 64;
#pragma unroll
    for (int mt = 0; mt < 2; ++mt) {
        const int s0 = s_base + mt * 16;
#pragma unroll
        for (int nt = 0; nt < 8; ++nt) {
            const int n0 = n_base + nt * 8 + 2 * (lane & 3);
            const float bv0 = bias[n0];
            const float bv1 = bias[n0 + 1];
            const size_t r0 = ((size_t)b_ * S + s0) * H + n0;
            const size_t r1 = ((size_t)b_ * S + s0 + 8) * H + n0;
            split_store2(&g_Ench[r0], &g_Encl[r0],
                         tanhf(acc[mt][nt][0] + bv0), tanhf(acc[mt][nt][1] + bv1));
            split_store2(&g_Ench[r1], &g_Encl[r1],
                         tanhf(acc[mt][nt][2] + bv0), tanhf(acc[mt][nt][3] + bv1));
        }
    }
}

// ---------------------------------------------------------------------------
// GEMM2: scores[b,t,s] = dec[b,t,:].enc[b,s,:] + ib[b,s], HMMA hi/lo 3-pass.
// CTA 64(t) x 64(s), BK=32, 2-stage cp.async; 4 warps = 2(M) x 2(N), warp 32x32.
// Grid (S/64, T/64, B) = (8, 4, 4) = 128 CTAs, 128 threads. Static 32 KB smem.
// ---------------------------------------------------------------------------
#define G2T_B (64 * 64)            // 4 KB per tile
#define G2STAGE (4 * G2T_B)        // 16 KB

__global__ __launch_bounds__(128, 1) void gemm2_mma(const float* __restrict__ ib)
{
    __shared__ __align__(128) char smem[2 * G2STAGE];   // 32 KB
    const uint32_t sb = smem_to_u32(smem);
    const int tid = threadIdx.x;
    const int lane = tid & 31;
    const int wid = tid >> 5;
    const int wm = wid & 1;           // 0..1 (M/t)
    const int wn = wid >> 1;          // 0..1 (N/s)
    const int b  = blockIdx.z;
    const int bt = blockIdx.y * 64;
    const int bs = blockIdx.x * 64;

    const unsigned short* srcs[4] = {
        g_Dech + (size_t)b * T * H, g_Decl + (size_t)b * T * H,
        g_Ench + (size_t)b * S * H, g_Encl + (size_t)b * S * H};

    float acc[2][4][4];
#pragma unroll
    for (int mt = 0; mt < 2; mt++)
#pragma unroll
        for (int nt = 0; nt < 4; nt++)
#pragma unroll
            for (int q = 0; q < 4; q++) acc[mt][nt][q] = 0.f;

    const int arow = lane & 15;
    const int half = lane >> 4;

#define G2_ISSUE(ch, stage)                                                    \
    do {                                                                       \
        const int _k0 = (ch) * BK1;                                            \
        _Pragma("unroll")                                                      \
        for (int _i = 0; _i < 8; _i++) {                                       \
            const int _u = tid + (_i << 7);                                    \
            const int _t = _u >> 8;                                            \
            const int _rem = _u & 255;                                         \
            const int _row = _rem >> 2;                                        \
            const int _c = _rem & 3;                                           \
            const int _grow = ((_t < 2) ? bt : bs) + _row;                     \
            const void* _g = srcs[_t] + (size_t)_grow * H + _k0 + _c * 8;      \
            const uint32_t _sa = sb + (stage) * G2STAGE + _t * G2T_B           \
                + _row * 64 + (((_c) ^ ((_row >> 1) & 3)) << 4);               \
            asm volatile("cp.async.cg.shared.global [%0], [%1], 16;"           \
                :: "r"(_sa), "l"(_g));                                         \
        }                                                                      \
        asm volatile("cp.async.commit_group;" ::: "memory");                   \
    } while (0)

    G2_ISSUE(0, 0);

    const int NCH = H / BK1;  // 32
    for (int ch = 0; ch < NCH; ++ch) {
        const int st = ch & 1;
        if (ch + 1 < NCH) {
            G2_ISSUE(ch + 1, st ^ 1);
            asm volatile("cp.async.wait_group 1;" ::: "memory");
        } else {
            asm volatile("cp.async.wait_group 0;" ::: "memory");
        }
        __syncthreads();

        const uint32_t base = sb + st * G2STAGE;
#pragma unroll
        for (int ks = 0; ks < 2; ++ks) {
            const int cb = ks * 2 + half;
            uint32_t ah[2][4], al[2][4];
#pragma unroll
            for (int mt = 0; mt < 2; ++mt) {
                const int row = wm * 32 + mt * 16 + arow;
                const uint32_t off = row * 64 + ((cb ^ ((row >> 1) & 3)) << 4);
                LDSM4(ah[mt], base + 0 * G2T_B + off);
                LDSM4(al[mt], base + 1 * G2T_B + off);
            }
#pragma unroll
            for (int np = 0; np < 2; ++np) {
                const int row = wn * 32 + np * 16 + arow;
                const uint32_t off = row * 64 + ((cb ^ ((row >> 1) & 3)) << 4);
                uint32_t bh[4], bl[4];
                LDSM4(bh, base + 2 * G2T_B + off);
                LDSM4(bl, base + 3 * G2T_B + off);
#pragma unroll
                for (int mt = 0; mt < 2; ++mt) {
                    MMA_BF16(acc[mt][2 * np],     ah[mt], bh[0], bh[2]);
                    MMA_BF16(acc[mt][2 * np],     al[mt], bh[0], bh[2]);
                    MMA_BF16(acc[mt][2 * np],     ah[mt], bl[0], bl[2]);
                    MMA_BF16(acc[mt][2 * np + 1], ah[mt], bh[1], bh[3]);
                    MMA_BF16(acc[mt][2 * np + 1], al[mt], bh[1], bh[3]);
                    MMA_BF16(acc[mt][2 * np + 1], ah[mt], bl[1], bl[3]);
                }
            }
        }
        __syncthreads();
    }

    // Epilogue: + input_bias, fp32 scores.
    const int t_base = bt + wm * 32 + (lane >> 2);
    const int s_col  = bs + wn * 32;
#pragma unroll
    for (int mt = 0; mt < 2; ++mt) {
        const int t0 = t_base + mt * 16;
#pragma unroll
        for (int nt = 0; nt < 4; ++nt) {
            const int s = s_col + nt * 8 + 2 * (lane & 3);
            const float b0 = ib[b * S + s];
            const float b1 = ib[b * S + s + 1];
            float2 v0 = make_float2(acc[mt][nt][0] + b0, acc[mt][nt][1] + b1);
            float2 v1 = make_float2(acc[mt][nt][2] + b0, acc[mt][nt][3] + b1);
            *(float2*)&g_scores[((size_t)b * T + t0) * S + s] = v0;
            *(float2*)&g_scores[((size_t)b * T + t0 + 8) * S + s] = v1;
        }
    }
}

// ---------------------------------------------------------------------------
// Kernel 3 (unchanged): zero vocab slice, softmax over S, scatter-add.
// ---------------------------------------------------------------------------
__global__ __launch_bounds__(256) void softmax_scatter(
    const int* __restrict__ ids, float* __restrict__ out)
{
    const int bt = blockIdx.x;
    const int b = bt / T;
    const int tid = threadIdx.x;

    const float* row = &g_scores[(size_t)bt * S];
    float* orow = out + (size_t)bt * V;

    const float4 z = make_float4(0.f, 0.f, 0.f, 0.f);
    float4* orow4 = (float4*)orow;
    for (int i = tid; i < V / 4; i += 256) orow4[i] = z;

    __shared__ float sm[S];
    __shared__ float red[256];

    float m = -INFINITY;
    for (int s = tid; s < S; s += 256) {
        float v = row[s];
        sm[s] = v;
        m = fmaxf(m, v);
    }
    red[tid] = m;
    __syncthreads();
    for (int off = 128; off > 0; off >>= 1) {
        if (tid < off) red[tid] = fmaxf(red[tid], red[tid + off]);
        __syncthreads();
    }
    const float mx = red[0];
    __syncthreads();

    float sum = 0.f;
    for (int s = tid; s < S; s += 256) {
        float e = expf(sm[s] - mx);
        sm[s] = e;
        sum += e;
    }
    red[tid] = sum;
    __syncthreads();
    for (int off = 128; off > 0; off >>= 1) {
        if (tid < off) red[tid] += red[tid + off];
        __syncthreads();
    }
    const float inv = 1.0f / red[0];
    __syncthreads();

    const int* brow = ids + b * S;
    for (int s = tid; s < S; s += 256) {
        atomicAdd(&orow[brow[s]], sm[s] * inv);
    }
}

// ---------------------------------------------------------------------------
extern "C" void kernel_launch(void* const* d_in, const int* in_sizes, int n_in,
                              void* d_out, int out_size)
{
    const int*   inputs = (const int*)d_in[0];    // [B,S] int32
    const float* E      = (const float*)d_in[1];  // [B,S,H]
    const float* Dec    = (const float*)d_in[2];  // [B,T,H]
    const float* ib     = (const float*)d_in[3];  // [B,S]
    const float* Wp     = (const float*)d_in[4];  // [H,H]
    const float* bp     = (const float*)d_in[5];  // [H]
    float* out = (float*)d_out;                   // [B,T,V]

    cudaFuncSetAttribute(gemm1_mma, cudaFuncAttributeMaxDynamicSharedMemorySize,
                         SMEM_G1);

    // Converters
    unsigned short *eh, *el, *dh, *dl;
    cudaGetSymbolAddress((void**)&eh, g_Eh);
    cudaGetSymbolAddress((void**)&el, g_El);
    cudaGetSymbolAddress((void**)&dh, g_Dech);
    cudaGetSymbolAddress((void**)&dl, g_Decl);

    convert_split<<<(M1 * H / 4) / 256, 256>>>(E, eh, el);
    convert_split<<<(B * T * H / 4) / 256, 256>>>(Dec, dh, dl);
    convert_W<<<dim3(H / 32, H / 32), 256>>>(Wp);

    dim3 g1(H / 128, M1 / 128);                   // (8, 16) = 128 CTAs
    gemm1_mma<<<g1, 256, SMEM_G1>>>(bp);

    dim3 g2(S / 64, T / 64, B);                   // (8, 4, 4) = 128 CTAs
    gemm2_mma<<<g2, 128>>>(ib);

    softmax_scatter<<<B * T, 256>>>(inputs, out);
}

// round 8
// speedup vs baseline: 2.5916x; 1.0247x over previous
#include <cuda_runtime.h>
#include <cuda_bf16.h>
#include <math.h>
#include <cstdint>

// Problem constants (fixed shapes)
#define B 4
#define S 512
#define T 256
#define H 1024
#define V 32000
#define M1 (B * S)   // 2048

// Scratch (device globals — no allocations allowed)
__device__ float g_scores[B * T * S];        // [b][t][s], 2 MB
__device__ unsigned short g_Eh[M1 * H];      // bf16 hi of E   [M,K]
__device__ unsigned short g_El[M1 * H];      // bf16 lo of E   [M,K]
__device__ unsigned short g_Wh[H * H];       // bf16 hi of W^T [N,K]
__device__ unsigned short g_Wl[H * H];       // bf16 lo of W^T [N,K]
__device__ unsigned short g_Ench[B * S * H]; // bf16 hi of enc [b][s][h]
__device__ unsigned short g_Encl[B * S * H]; // bf16 lo of enc [b][s][h]
__device__ unsigned short g_Dech[B * T * H]; // bf16 hi of dec [b][t][h]
__device__ unsigned short g_Decl[B * T * H]; // bf16 lo of dec [b][t][h]

// ---------------------------------------------------------------------------
// Arch-generic tensor-core primitives (legal on plain sm_103 target)
// ---------------------------------------------------------------------------
#define LDSM4(r, a)                                                            \
    asm volatile("ldmatrix.sync.aligned.m8n8.x4.shared.b16 {%0,%1,%2,%3}, [%4];" \
        : "=r"((r)[0]), "=r"((r)[1]), "=r"((r)[2]), "=r"((r)[3]) : "r"(a))

#define MMA_BF16(d, a, b0, b1)                                                 \
    asm volatile(                                                              \
        "mma.sync.aligned.m16n8k16.row.col.f32.bf16.bf16.f32 "                 \
        "{%0,%1,%2,%3}, {%4,%5,%6,%7}, {%8,%9}, {%0,%1,%2,%3};"                \
        : "+f"((d)[0]), "+f"((d)[1]), "+f"((d)[2]), "+f"((d)[3])               \
        : "r"((a)[0]), "r"((a)[1]), "r"((a)[2]), "r"((a)[3]),                  \
          "r"(b0), "r"(b1))

__device__ __forceinline__ uint32_t smem_to_u32(const void* p) {
    uint32_t a;
    asm("{ .reg .u64 t; cvta.to.shared.u64 t, %1; cvt.u32.u64 %0, t; }"
        : "=r"(a) : "l"(p));
    return a;
}

__device__ __forceinline__ void split_store2(
    unsigned short* hp, unsigned short* lp, float v0, float v1)
{
    __nv_bfloat16 h0 = __float2bfloat16_rn(v0);
    __nv_bfloat16 h1 = __float2bfloat16_rn(v1);
    unsigned short l0 = __bfloat16_as_ushort(__float2bfloat16_rn(v0 - __bfloat162float(h0)));
    unsigned short l1 = __bfloat16_as_ushort(__float2bfloat16_rn(v1 - __bfloat162float(h1)));
    *(uint32_t*)hp = (uint32_t)__bfloat16_as_ushort(h0) |
                     ((uint32_t)__bfloat16_as_ushort(h1) << 16);
    *(uint32_t*)lp = (uint32_t)l0 | ((uint32_t)l1 << 16);
}

// ---------------------------------------------------------------------------
// Converters: fp32 -> bf16 hi/lo
// ---------------------------------------------------------------------------
__global__ __launch_bounds__(256) void convert_split(
    const float* __restrict__ src, unsigned short* __restrict__ hi,
    unsigned short* __restrict__ lo)
{
    const int idx = blockIdx.x * 256 + threadIdx.x;
    const float4 v = ((const float4*)src)[idx];
    ushort4 h, l;
    const float* vf = (const float*)&v;
    unsigned short* hp = (unsigned short*)&h;
    unsigned short* lp = (unsigned short*)&l;
#pragma unroll
    for (int i = 0; i < 4; i++) {
        __nv_bfloat16 hb = __float2bfloat16_rn(vf[i]);
        hp[i] = __bfloat16_as_ushort(hb);
        lp[i] = __bfloat16_as_ushort(__float2bfloat16_rn(vf[i] - __bfloat162float(hb)));
    }
    ((ushort4*)hi)[idx] = h;
    ((ushort4*)lo)[idx] = l;
}

__global__ __launch_bounds__(256) void convert_W(const float* __restrict__ W)
{
    __shared__ float t[32][33];
    const int k0 = blockIdx.x * 32;
    const int n0 = blockIdx.y * 32;
    const int tx = threadIdx.x & 31;
    const int ty = threadIdx.x >> 5;
#pragma unroll
    for (int r = 0; r < 4; r++) {
        const int k = ty + r * 8;
        t[k][tx] = W[(size_t)(k0 + k) * H + n0 + tx];
    }
    __syncthreads();
#pragma unroll
    for (int r = 0; r < 4; r++) {
        const int n = ty + r * 8;
        const float x = t[tx][n];
        __nv_bfloat16 hb = __float2bfloat16_rn(x);
        g_Wh[(size_t)(n0 + n) * H + k0 + tx] = __bfloat16_as_ushort(hb);
        g_Wl[(size_t)(n0 + n) * H + k0 + tx] =
            __bfloat16_as_ushort(__float2bfloat16_rn(x - __bfloat162float(hb)));
    }
}

// ---------------------------------------------------------------------------
// GEMM1: enc = tanh(E @ W + b), HMMA bf16 hi/lo 3-pass.
// CTA tile 64(M) x 128(N), BK=32, 2-stage cp.async, 48 KB static smem,
// 2 CTAs/SM. 8 warps = 2(M) x 4(N); warp tile 32x32.
// Grid (H/128, M1/64) = (8, 32) = 256 CTAs.
// ---------------------------------------------------------------------------
#define BK1 32
#define G1_TA 4096                 // A tile: 64 rows x 64 B
#define G1_TB 8192                 // B tile: 128 rows x 64 B
#define G1_STAGE (2 * G1_TA + 2 * G1_TB)   // 24 KB: [Ah, Al, Bh, Bl]

__global__ __launch_bounds__(256, 2) void gemm1_mma(const float* __restrict__ bias)
{
    __shared__ __align__(128) char smem[2 * G1_STAGE];   // 48 KB
    const uint32_t sb = smem_to_u32(smem);
    const int tid = threadIdx.x;
    const int lane = tid & 31;
    const int wid = tid >> 5;
    const int wm = wid & 1;           // 0..1 (M)
    const int wn = wid >> 1;          // 0..3 (N)
    const int bm = blockIdx.y * 64;   // (b,s) tile
    const int bn = blockIdx.x * 128;  // h tile

    float acc[2][4][4];
#pragma unroll
    for (int mt = 0; mt < 2; mt++)
#pragma unroll
        for (int nt = 0; nt < 4; nt++)
#pragma unroll
            for (int q = 0; q < 4; q++) acc[mt][nt][q] = 0.f;

    const int arow = lane & 15;
    const int half = lane >> 4;

    // 1536 16B-units per stage: [0,256)=Ah, [256,512)=Al, [512,1024)=Bh, [1024,1536)=Bl
#define G1_ISSUE(ch, stage)                                                    \
    do {                                                                       \
        const int _k0 = (ch) * BK1;                                            \
        _Pragma("unroll")                                                      \
        for (int _i = 0; _i < 6; _i++) {                                       \
            const int _u = tid + (_i << 8);                                    \
            const unsigned short* _src;                                        \
            uint32_t _tb; int _rr, _gr;                                        \
            if (_u < 512) {                                                    \
                _src = (_u < 256) ? g_Eh : g_El;                               \
                _tb = (_u < 256) ? 0u : (uint32_t)G1_TA;                       \
                _rr = (_u & 255) >> 2;                                         \
                _gr = bm + _rr;                                                \
            } else {                                                           \
                _src = (_u < 1024) ? g_Wh : g_Wl;                              \
                _tb = (_u < 1024) ? (uint32_t)(2 * G1_TA)                      \
                                  : (uint32_t)(2 * G1_TA + G1_TB);             \
                _rr = (_u & 511) >> 2;                                         \
                _gr = bn + _rr;                                                \
            }                                                                  \
            const int _c = _u & 3;                                             \
            const void* _g = _src + (size_t)_gr * H + _k0 + _c * 8;            \
            const uint32_t _sa = sb + (stage) * G1_STAGE + _tb                 \
                + _rr * 64 + (((_c) ^ ((_rr >> 1) & 3)) << 4);                 \
            asm volatile("cp.async.cg.shared.global [%0], [%1], 16;"           \
                :: "r"(_sa), "l"(_g));                                         \
        }                                                                      \
        asm volatile("cp.async.commit_group;" ::: "memory");                   \
    } while (0)

    G1_ISSUE(0, 0);

    const int NCH = H / BK1;  // 32
    for (int ch = 0; ch < NCH; ++ch) {
        const int st = ch & 1;
        if (ch + 1 < NCH) {
            G1_ISSUE(ch + 1, st ^ 1);
            asm volatile("cp.async.wait_group 1;" ::: "memory");
        } else {
            asm volatile("cp.async.wait_group 0;" ::: "memory");
        }
        __syncthreads();

        const uint32_t base = sb + st * G1_STAGE;
#pragma unroll
        for (int ks = 0; ks < 2; ++ks) {
            const int cb = ks * 2 + half;
            uint32_t ah[2][4], al[2][4];
#pragma unroll
            for (int mt = 0; mt < 2; ++mt) {
                const int row = wm * 32 + mt * 16 + arow;
                const uint32_t off = row * 64 + ((cb ^ ((row >> 1) & 3)) << 4);
                LDSM4(ah[mt], base + off);
                LDSM4(al[mt], base + G1_TA + off);
            }
#pragma unroll
            for (int np = 0; np < 2; ++np) {
                const int row = wn * 32 + np * 16 + arow;
                const uint32_t off = row * 64 + ((cb ^ ((row >> 1) & 3)) << 4);
                uint32_t bh[4], bl[4];
                LDSM4(bh, base + 2 * G1_TA + off);
                LDSM4(bl, base + 2 * G1_TA + G1_TB + off);
#pragma unroll
                for (int mt = 0; mt < 2; ++mt) {
                    MMA_BF16(acc[mt][2 * np],     ah[mt], bh[0], bh[2]);
                    MMA_BF16(acc[mt][2 * np],     al[mt], bh[0], bh[2]);
                    MMA_BF16(acc[mt][2 * np],     ah[mt], bl[0], bl[2]);
                    MMA_BF16(acc[mt][2 * np + 1], ah[mt], bh[1], bh[3]);
                    MMA_BF16(acc[mt][2 * np + 1], al[mt], bh[1], bh[3]);
                    MMA_BF16(acc[mt][2 * np + 1], ah[mt], bl[1], bl[3]);
                }
            }
        }
        __syncthreads();
    }

    // Epilogue: tanh(D + bias[h]) split to bf16 hi/lo, stored [b][s][h].
    const int b_ = bm / S;
    const int s_base = (bm % S) + wm * 32 + (lane >> 2);
    const int n_base = bn + wn * 32;
#pragma unroll
    for (int mt = 0; mt < 2; ++mt) {
        const int s0 = s_base + mt * 16;
#pragma unroll
        for (int nt = 0; nt < 4; ++nt) {
            const int n0 = n_base + nt * 8 + 2 * (lane & 3);
            const float bv0 = bias[n0];
            const float bv1 = bias[n0 + 1];
            const size_t r0 = ((size_t)b_ * S + s0) * H + n0;
            const size_t r1 = ((size_t)b_ * S + s0 + 8) * H + n0;
            split_store2(&g_Ench[r0], &g_Encl[r0],
                         tanhf(acc[mt][nt][0] + bv0), tanhf(acc[mt][nt][1] + bv1));
            split_store2(&g_Ench[r1], &g_Encl[r1],
                         tanhf(acc[mt][nt][2] + bv0), tanhf(acc[mt][nt][3] + bv1));
        }
    }
}

// ---------------------------------------------------------------------------
// GEMM2: scores[b,t,s] = dec.enc + ib, HMMA hi/lo 3-pass (unchanged from R6).
// CTA 64x64, BK=32, 2-stage cp.async; 4 warps = 2x2, warp 32x32.
// ---------------------------------------------------------------------------
#define G2T_B (64 * 64)
#define G2STAGE (4 * G2T_B)

__global__ __launch_bounds__(128, 1) void gemm2_mma(const float* __restrict__ ib)
{
    __shared__ __align__(128) char smem[2 * G2STAGE];   // 32 KB
    const uint32_t sb = smem_to_u32(smem);
    const int tid = threadIdx.x;
    const int lane = tid & 31;
    const int wid = tid >> 5;
    const int wm = wid & 1;
    const int wn = wid >> 1;
    const int b  = blockIdx.z;
    const int bt = blockIdx.y * 64;
    const int bs = blockIdx.x * 64;

    const unsigned short* srcs[4] = {
        g_Dech + (size_t)b * T * H, g_Decl + (size_t)b * T * H,
        g_Ench + (size_t)b * S * H, g_Encl + (size_t)b * S * H};

    float acc[2][4][4];
#pragma unroll
    for (int mt = 0; mt < 2; mt++)
#pragma unroll
        for (int nt = 0; nt < 4; nt++)
#pragma unroll
            for (int q = 0; q < 4; q++) acc[mt][nt][q] = 0.f;

    const int arow = lane & 15;
    const int half = lane >> 4;

#define G2_ISSUE(ch, stage)                                                    \
    do {                                                                       \
        const int _k0 = (ch) * BK1;                                            \
        _Pragma("unroll")                                                      \
        for (int _i = 0; _i < 8; _i++) {                                       \
            const int _u = tid + (_i << 7);                                    \
            const int _t = _u >> 8;                                            \
            const int _rem = _u & 255;                                         \
            const int _row = _rem >> 2;                                        \
            const int _c = _rem & 3;                                           \
            const int _grow = ((_t < 2) ? bt : bs) + _row;                     \
            const void* _g = srcs[_t] + (size_t)_grow * H + _k0 + _c * 8;      \
            const uint32_t _sa = sb + (stage) * G2STAGE + _t * G2T_B           \
                + _row * 64 + (((_c) ^ ((_row >> 1) & 3)) << 4);               \
            asm volatile("cp.async.cg.shared.global [%0], [%1], 16;"           \
                :: "r"(_sa), "l"(_g));                                         \
        }                                                                      \
        asm volatile("cp.async.commit_group;" ::: "memory");                   \
    } while (0)

    G2_ISSUE(0, 0);

    const int NCH = H / BK1;
    for (int ch = 0; ch < NCH; ++ch) {
        const int st = ch & 1;
        if (ch + 1 < NCH) {
            G2_ISSUE(ch + 1, st ^ 1);
            asm volatile("cp.async.wait_group 1;" ::: "memory");
        } else {
            asm volatile("cp.async.wait_group 0;" ::: "memory");
        }
        __syncthreads();

        const uint32_t base = sb + st * G2STAGE;
#pragma unroll
        for (int ks = 0; ks < 2; ++ks) {
            const int cb = ks * 2 + half;
            uint32_t ah[2][4], al[2][4];
#pragma unroll
            for (int mt = 0; mt < 2; ++mt) {
                const int row = wm * 32 + mt * 16 + arow;
                const uint32_t off = row * 64 + ((cb ^ ((row >> 1) & 3)) << 4);
                LDSM4(ah[mt], base + 0 * G2T_B + off);
                LDSM4(al[mt], base + 1 * G2T_B + off);
            }
#pragma unroll
            for (int np = 0; np < 2; ++np) {
                const int row = wn * 32 + np * 16 + arow;
                const uint32_t off = row * 64 + ((cb ^ ((row >> 1) & 3)) << 4);
                uint32_t bh[4], bl[4];
                LDSM4(bh, base + 2 * G2T_B + off);
                LDSM4(bl, base + 3 * G2T_B + off);
#pragma unroll
                for (int mt = 0; mt < 2; ++mt) {
                    MMA_BF16(acc[mt][2 * np],     ah[mt], bh[0], bh[2]);
                    MMA_BF16(acc[mt][2 * np],     al[mt], bh[0], bh[2]);
                    MMA_BF16(acc[mt][2 * np],     ah[mt], bl[0], bl[2]);
                    MMA_BF16(acc[mt][2 * np + 1], ah[mt], bh[1], bh[3]);
                    MMA_BF16(acc[mt][2 * np + 1], al[mt], bh[1], bh[3]);
                    MMA_BF16(acc[mt][2 * np + 1], ah[mt], bl[1], bl[3]);
                }
            }
        }
        __syncthreads();
    }

    const int t_base = bt + wm * 32 + (lane >> 2);
    const int s_col  = bs + wn * 32;
#pragma unroll
    for (int mt = 0; mt < 2; ++mt) {
        const int t0 = t_base + mt * 16;
#pragma unroll
        for (int nt = 0; nt < 4; ++nt) {
            const int s = s_col + nt * 8 + 2 * (lane & 3);
            const float b0 = ib[b * S + s];
            const float b1 = ib[b * S + s + 1];
            float2 v0 = make_float2(acc[mt][nt][0] + b0, acc[mt][nt][1] + b1);
            float2 v1 = make_float2(acc[mt][nt][2] + b0, acc[mt][nt][3] + b1);
            *(float2*)&g_scores[((size_t)b * T + t0) * S + s] = v0;
            *(float2*)&g_scores[((size_t)b * T + t0 + 8) * S + s] = v1;
        }
    }
}

// ---------------------------------------------------------------------------
// Kernel 3: 512 threads — zero vocab slice, softmax over S (1 elt/thread),
// scatter-add. Warp-shuffle reductions.
// ---------------------------------------------------------------------------
__global__ __launch_bounds__(512) void softmax_scatter(
    const int* __restrict__ ids, float* __restrict__ out)
{
    const int bt = blockIdx.x;
    const int b = bt / T;
    const int tid = threadIdx.x;

    const float* row = &g_scores[(size_t)bt * S];
    float* orow = out + (size_t)bt * V;

    // Zero the vocab slice (8000 float4 over 512 threads)
    const float4 z = make_float4(0.f, 0.f, 0.f, 0.f);
    float4* orow4 = (float4*)orow;
#pragma unroll 4
    for (int i = tid; i < V / 4; i += 512) orow4[i] = z;

    __shared__ float red[16];

    // One score element per thread
    float v = row[tid];

    // Max reduce: warp shuffle, then cross-warp via smem
    float m = v;
#pragma unroll
    for (int o = 16; o > 0; o >>= 1)
        m = fmaxf(m, __shfl_xor_sync(0xFFFFFFFFu, m, o));
    if ((tid & 31) == 0) red[tid >> 5] = m;
    __syncthreads();
    if (tid < 16) {
        float t = red[tid];
#pragma unroll
        for (int o = 8; o > 0; o >>= 1)
            t = fmaxf(t, __shfl_xor_sync(0xFFFFu, t, o));
        red[tid] = t;
    }
    __syncthreads();
    const float mx = red[0];

    // Exp + sum reduce
    float e = expf(v - mx);
    float s = e;
#pragma unroll
    for (int o = 16; o > 0; o >>= 1)
        s += __shfl_xor_sync(0xFFFFFFFFu, s, o);
    __syncthreads();
    if ((tid & 31) == 0) red[tid >> 5] = s;
    __syncthreads();
    if (tid < 16) {
        float t = red[tid];
#pragma unroll
        for (int o = 8; o > 0; o >>= 1)
            t += __shfl_xor_sync(0xFFFFu, t, o);
        red[tid] = t;
    }
    __syncthreads();
    const float inv = 1.0f / red[0];

    // Scatter (zeroing stores above are ordered by the __syncthreads chain)
    atomicAdd(&orow[ids[b * S + tid]], e * inv);
}

// ---------------------------------------------------------------------------
extern "C" void kernel_launch(void* const* d_in, const int* in_sizes, int n_in,
                              void* d_out, int out_size)
{
    const int*   inputs = (const int*)d_in[0];    // [B,S] int32
    const float* E      = (const float*)d_in[1];  // [B,S,H]
    const float* Dec    = (const float*)d_in[2];  // [B,T,H]
    const float* ib     = (const float*)d_in[3];  // [B,S]
    const float* Wp     = (const float*)d_in[4];  // [H,H]
    const float* bp     = (const float*)d_in[5];  // [H]
    float* out = (float*)d_out;                   // [B,T,V]

    unsigned short *eh, *el, *dh, *dl;
    cudaGetSymbolAddress((void**)&eh, g_Eh);
    cudaGetSymbolAddress((void**)&el, g_El);
    cudaGetSymbolAddress((void**)&dh, g_Dech);
    cudaGetSymbolAddress((void**)&dl, g_Decl);

    convert_split<<<(M1 * H / 4) / 256, 256>>>(E, eh, el);
    convert_split<<<(B * T * H / 4) / 256, 256>>>(Dec, dh, dl);
    convert_W<<<dim3(H / 32, H / 32), 256>>>(Wp);

    dim3 g1(H / 128, M1 / 64);                    // (8, 32) = 256 CTAs
    gemm1_mma<<<g1, 256>>>(bp);

    dim3 g2(S / 64, T / 64, B);                   // (8, 4, 4) = 128 CTAs
    gemm2_mma<<<g2, 128>>>(ib);

    softmax_scatter<<<B * T, 512>>>(inputs, out);
}